// round 8
// baseline (speedup 1.0000x reference)
#include <cuda_runtime.h>
#include <cstdint>

#define BQ   2
#define NCAM 6
#define CCH  256
#define MQ   900
#define NLVL 4
#define EPSV 1e-5f

__constant__ int c_H[NLVL]  = {116, 58, 29, 15};
__constant__ int c_W[NLVL]  = {200, 100, 50, 25};
__constant__ int c_HW[NLVL] = {23200, 5800, 1450, 375};

#define NENT   (NCAM * NLVL)   // 24 real entries
#define NSLOT  (NENT + 1)      // +1 dummy slot for padding
#define DUMMY  NENT

__global__ __launch_bounds__(CCH, 5)
void FeatureSampler_kernel(const float* __restrict__ f0,
                           const float* __restrict__ f1,
                           const float* __restrict__ f2,
                           const float* __restrict__ f3,
                           const float* __restrict__ refpts,
                           const float* __restrict__ l2i,
                           float* __restrict__ out)
{
    const int bm  = blockIdx.x;          // b * MQ + m
    const int b   = bm / MQ;
    const int L   = threadIdx.x & 31;    // lane
    const int wrp = threadIdx.x >> 5;    // warp 0..7

    // corner in low 2 lane bits: lanes 0/1 (x0,x1 row y0) coalesce to one
    // sector, lanes 2/3 likewise for row y1.
    const int corner = L & 3;
    const int chsub  = wrp * 8 + (L >> 2);   // channel sub-index 0..63

    __shared__ const float* s_base[NSLOT];
    __shared__ int   s_HW[NSLOT];
    __shared__ int   s_idx[NSLOT][4];
    __shared__ float s_w[NSLOT][4];
    __shared__ int   s_act[NENT];
    __shared__ float s_valid[NCAM];
    __shared__ int   s_list[NENT + 4];   // padded to multiple of 4
    __shared__ int   s_ne;

    // ---- Phase 1: threads 0..23 build per-(camera,level) sampling entries ----
    if (threadIdx.x < NENT) {
        const int t   = threadIdx.x;
        const int n   = t >> 2;
        const int lvl = t & 3;

        const float* rp = refpts + (size_t)bm * 3;
        float rx = rp[0] * 122.4f - 61.2f;
        float ry = rp[1] * 122.4f - 61.2f;
        float rz = rp[2] * 20.0f  - 10.0f;

        const float* Mt = l2i + (size_t)(b * NCAM + n) * 16;
        float cx = Mt[0]*rx + Mt[1]*ry + Mt[2] *rz + Mt[3];
        float cy = Mt[4]*rx + Mt[5]*ry + Mt[6] *rz + Mt[7];
        float cz = Mt[8]*rx + Mt[9]*ry + Mt[10]*rz + Mt[11];

        bool vcam = (cz > EPSV);
        if (lvl == 0) s_valid[n] = vcam ? 1.0f : 0.0f;

        float inv = 1.0f / (cz + EPSV);
        float x = cx * inv - 0.5f;   // grid_sample denorm cancels across levels
        float y = cy * inv - 0.5f;

        const int W  = c_W[lvl];
        const int H  = c_H[lvl];
        const int HW = c_HW[lvl];

        int active = 0;
        if (vcam && (x > -1.0f) && (x < (float)W) && (y > -1.0f) && (y < (float)H)) {
            float x0f = floorf(x), y0f = floorf(y);
            float wx1 = x - x0f, wx0 = 1.0f - wx1;
            float wy1 = y - y0f, wy0 = 1.0f - wy1;

            bool vx0 = (x0f >= 0.0f)        && (x0f <= (float)(W - 1));
            bool vx1 = (x0f + 1.0f >= 0.0f) && (x0f + 1.0f <= (float)(W - 1));
            bool vy0 = (y0f >= 0.0f)        && (y0f <= (float)(H - 1));
            bool vy1 = (y0f + 1.0f >= 0.0f) && (y0f + 1.0f <= (float)(H - 1));

            int xi0 = (int)fminf(fmaxf(x0f,        0.0f), (float)(W - 1));
            int xi1 = (int)fminf(fmaxf(x0f + 1.0f, 0.0f), (float)(W - 1));
            int yi0 = (int)fminf(fmaxf(y0f,        0.0f), (float)(H - 1));
            int yi1 = (int)fminf(fmaxf(y0f + 1.0f, 0.0f), (float)(H - 1));

            float w00 = (vx0 && vy0) ? (wx0 * wy0) : 0.0f;
            float w01 = (vx1 && vy0) ? (wx1 * wy0) : 0.0f;
            float w10 = (vx0 && vy1) ? (wx0 * wy1) : 0.0f;
            float w11 = (vx1 && vy1) ? (wx1 * wy1) : 0.0f;

            if ((w00 != 0.0f) || (w01 != 0.0f) || (w10 != 0.0f) || (w11 != 0.0f)) {
                active = 1;
                const float* fl = (lvl == 0) ? f0 : (lvl == 1) ? f1 : (lvl == 2) ? f2 : f3;
                s_base[t]   = fl + (size_t)(b * NCAM + n) * CCH * HW;
                s_HW[t]     = HW;
                s_idx[t][0] = yi0 * W + xi0;
                s_idx[t][1] = yi0 * W + xi1;
                s_idx[t][2] = yi1 * W + xi0;
                s_idx[t][3] = yi1 * W + xi1;
                s_w[t][0] = w00;  s_w[t][1] = w01;
                s_w[t][2] = w10;  s_w[t][3] = w11;
            }
        }
        s_act[t] = active;
    } else if (threadIdx.x < NENT + 4 && threadIdx.x >= NENT) {
        // init dummy slot (one thread suffices; harmless if several write)
        s_base[DUMMY] = f0;
        s_HW[DUMMY] = 0;
        s_idx[DUMMY][0] = 0; s_idx[DUMMY][1] = 0;
        s_idx[DUMMY][2] = 0; s_idx[DUMMY][3] = 0;
        s_w[DUMMY][0] = 0.0f; s_w[DUMMY][1] = 0.0f;
        s_w[DUMMY][2] = 0.0f; s_w[DUMMY][3] = 0.0f;
    }
    __syncthreads();

    // ---- Deterministic compaction + pad to multiple of 4 with dummy ----
    if (threadIdx.x == 0) {
        int ne = 0;
        #pragma unroll
        for (int e = 0; e < NENT; e++)
            if (s_act[e]) s_list[ne++] = e;
        int ne4 = (ne + 3) & ~3;
        for (int k = ne; k < ne4; k++) s_list[k] = DUMMY;
        s_ne = ne4;
    }
    __syncthreads();

    const float cnt = s_valid[0] + s_valid[1] + s_valid[2] +
                      s_valid[3] + s_valid[4] + s_valid[5];
    const int ne4 = s_ne;

    // ---- Phase 2: batches of 4 entries, 16 independent LDGs in flight ----
    float acc0 = 0.0f, acc1 = 0.0f, acc2 = 0.0f, acc3 = 0.0f;

    for (int kb = 0; kb < ne4; kb += 4) {
        const float* p[4];
        int   hw[4];
        float w[4];
        #pragma unroll
        for (int j = 0; j < 4; j++) {
            const int e = s_list[kb + j];
            hw[j] = s_HW[e];
            w[j]  = s_w[e][corner];
            p[j]  = s_base[e] + (size_t)chsub * hw[j] + s_idx[e][corner];
        }

        float v[16];
        #pragma unroll
        for (int j = 0; j < 4; j++) {
            v[j*4 + 0] = __ldg(p[j]);
            v[j*4 + 1] = __ldg(p[j] + (size_t)64  * hw[j]);
            v[j*4 + 2] = __ldg(p[j] + (size_t)128 * hw[j]);
            v[j*4 + 3] = __ldg(p[j] + (size_t)192 * hw[j]);
        }

        #pragma unroll
        for (int j = 0; j < 4; j++) {
            acc0 += v[j*4 + 0] * w[j];
            acc1 += v[j*4 + 1] * w[j];
            acc2 += v[j*4 + 2] * w[j];
            acc3 += v[j*4 + 3] * w[j];
        }
    }

    // single butterfly at the end: sum the 4 corners within each quad
    acc0 += __shfl_xor_sync(0xFFFFFFFFu, acc0, 1);
    acc1 += __shfl_xor_sync(0xFFFFFFFFu, acc1, 1);
    acc2 += __shfl_xor_sync(0xFFFFFFFFu, acc2, 1);
    acc3 += __shfl_xor_sync(0xFFFFFFFFu, acc3, 1);
    acc0 += __shfl_xor_sync(0xFFFFFFFFu, acc0, 2);
    acc1 += __shfl_xor_sync(0xFFFFFFFFu, acc1, 2);
    acc2 += __shfl_xor_sync(0xFFFFFFFFu, acc2, 2);
    acc3 += __shfl_xor_sync(0xFFFFFFFFu, acc3, 2);

    if (corner == 0) {
        const float s = 0.25f / (cnt + EPSV);
        float* o = out + (size_t)bm * CCH + chsub;
        o[0]   = acc0 * s;
        o[64]  = acc1 * s;
        o[128] = acc2 * s;
        o[192] = acc3 * s;
    }
}

extern "C" void kernel_launch(void* const* d_in, const int* in_sizes, int n_in,
                              void* d_out, int out_size)
{
    const float* f0  = (const float*)d_in[0];
    const float* f1  = (const float*)d_in[1];
    const float* f2  = (const float*)d_in[2];
    const float* f3  = (const float*)d_in[3];
    const float* rp  = (const float*)d_in[4];
    const float* l2i = (const float*)d_in[5];
    float* out = (float*)d_out;

    dim3 grid(BQ * MQ);
    dim3 block(CCH);
    FeatureSampler_kernel<<<grid, block>>>(f0, f1, f2, f3, rp, l2i, out);
}

// round 9
// speedup vs baseline: 1.1102x; 1.1102x over previous
#include <cuda_runtime.h>
#include <cstdint>

#define BQ   2
#define NCAM 6
#define CCH  256
#define MQ   900
#define NLVL 4
#define EPSV 1e-5f

__constant__ int c_H[NLVL]  = {116, 58, 29, 15};
__constant__ int c_W[NLVL]  = {200, 100, 50, 25};
__constant__ int c_HW[NLVL] = {23200, 5800, 1450, 375};

#define NENT (NCAM * NLVL)   // 24

__global__ __launch_bounds__(CCH, 6)
void FeatureSampler_kernel(const float* __restrict__ f0,
                           const float* __restrict__ f1,
                           const float* __restrict__ f2,
                           const float* __restrict__ f3,
                           const float* __restrict__ refpts,
                           const float* __restrict__ l2i,
                           float* __restrict__ out)
{
    const int bm  = blockIdx.x;          // b * MQ + m
    const int b   = bm / MQ;
    const int L   = threadIdx.x & 31;    // lane
    const int wrp = threadIdx.x >> 5;    // warp 0..7

    // corner in low 2 lane bits: lanes 0/1 (x0,x1 row y0) coalesce into one
    // 32B sector; lanes 2/3 likewise for row y1.
    const int corner = L & 3;
    const int chsub  = wrp * 8 + (L >> 2);   // channel sub-index 0..63

    __shared__ const float* s_ptr[NENT][4];  // base + corner index, precomputed
    __shared__ int   s_HW[NENT];
    __shared__ float s_w[NENT][4];
    __shared__ int   s_list[NENT];
    __shared__ int   s_ne;
    __shared__ float s_cnt;

    // ---- Phase 1 (warp 0 only): build entries + ballot compaction ----
    if (wrp == 0) {
        const int t   = L;               // entry index (only t<24 meaningful)
        const int n   = t >> 2;          // camera
        const int lvl = t & 3;           // level

        int active = 0;
        bool vcam  = false;

        if (t < NENT) {
            const float* rp = refpts + (size_t)bm * 3;
            float rx = rp[0] * 122.4f - 61.2f;
            float ry = rp[1] * 122.4f - 61.2f;
            float rz = rp[2] * 20.0f  - 10.0f;

            const float* Mt = l2i + (size_t)(b * NCAM + n) * 16;
            float cx = Mt[0]*rx + Mt[1]*ry + Mt[2] *rz + Mt[3];
            float cy = Mt[4]*rx + Mt[5]*ry + Mt[6] *rz + Mt[7];
            float cz = Mt[8]*rx + Mt[9]*ry + Mt[10]*rz + Mt[11];

            vcam = (cz > EPSV);

            float inv = 1.0f / (cz + EPSV);
            float x = cx * inv - 0.5f;   // grid_sample denorm cancels across levels
            float y = cy * inv - 0.5f;

            const int W  = c_W[lvl];
            const int H  = c_H[lvl];
            const int HW = c_HW[lvl];

            if (vcam && (x > -1.0f) && (x < (float)W) && (y > -1.0f) && (y < (float)H)) {
                float x0f = floorf(x), y0f = floorf(y);
                float wx1 = x - x0f, wx0 = 1.0f - wx1;
                float wy1 = y - y0f, wy0 = 1.0f - wy1;

                bool vx0 = (x0f >= 0.0f)        && (x0f <= (float)(W - 1));
                bool vx1 = (x0f + 1.0f >= 0.0f) && (x0f + 1.0f <= (float)(W - 1));
                bool vy0 = (y0f >= 0.0f)        && (y0f <= (float)(H - 1));
                bool vy1 = (y0f + 1.0f >= 0.0f) && (y0f + 1.0f <= (float)(H - 1));

                int xi0 = (int)fminf(fmaxf(x0f,        0.0f), (float)(W - 1));
                int xi1 = (int)fminf(fmaxf(x0f + 1.0f, 0.0f), (float)(W - 1));
                int yi0 = (int)fminf(fmaxf(y0f,        0.0f), (float)(H - 1));
                int yi1 = (int)fminf(fmaxf(y0f + 1.0f, 0.0f), (float)(H - 1));

                float w00 = (vx0 && vy0) ? (wx0 * wy0) : 0.0f;
                float w01 = (vx1 && vy0) ? (wx1 * wy0) : 0.0f;
                float w10 = (vx0 && vy1) ? (wx0 * wy1) : 0.0f;
                float w11 = (vx1 && vy1) ? (wx1 * wy1) : 0.0f;

                if ((w00 != 0.0f) || (w01 != 0.0f) || (w10 != 0.0f) || (w11 != 0.0f)) {
                    active = 1;
                    const float* fl = (lvl == 0) ? f0 : (lvl == 1) ? f1 :
                                      (lvl == 2) ? f2 : f3;
                    const float* base = fl + (size_t)(b * NCAM + n) * CCH * HW;
                    s_HW[t]     = HW;
                    s_ptr[t][0] = base + (yi0 * W + xi0);
                    s_ptr[t][1] = base + (yi0 * W + xi1);
                    s_ptr[t][2] = base + (yi1 * W + xi0);
                    s_ptr[t][3] = base + (yi1 * W + xi1);
                    s_w[t][0] = w00;  s_w[t][1] = w01;
                    s_w[t][2] = w10;  s_w[t][3] = w11;
                }
            }
        }

        // ballot compaction: O(1) instead of thread-0 serial loop
        unsigned amask = __ballot_sync(0xFFFFFFFFu, active != 0);
        if (active) {
            int pos = __popc(amask & ((1u << t) - 1u));
            s_list[pos] = t;
        }
        // camera-valid count: lanes with lvl==0 carry vcam
        unsigned vmask = __ballot_sync(0xFFFFFFFFu, vcam && (lvl == 0) && (t < NENT));
        if (L == 0) {
            s_ne  = __popc(amask);
            s_cnt = (float)__popc(vmask);
        }
    }
    __syncthreads();

    const int   ne  = s_ne;
    const float cnt = s_cnt;

    // ---- Phase 2: per-lane weighted accumulation (R6 structure, unroll x2) ----
    float acc0 = 0.0f, acc1 = 0.0f, acc2 = 0.0f, acc3 = 0.0f;

    int k = 0;
    for (; k + 1 < ne; k += 2) {
        const int ea = s_list[k];
        const int eb = s_list[k + 1];
        const int HWa = s_HW[ea];
        const int HWb = s_HW[eb];
        const float wa = s_w[ea][corner];
        const float wb = s_w[eb][corner];
        const float* pa = s_ptr[ea][corner] + (size_t)chsub * HWa;
        const float* pb = s_ptr[eb][corner] + (size_t)chsub * HWb;

        float a0 = __ldg(pa);
        float a1 = __ldg(pa + (size_t)64  * HWa);
        float a2 = __ldg(pa + (size_t)128 * HWa);
        float a3 = __ldg(pa + (size_t)192 * HWa);
        float b0 = __ldg(pb);
        float b1 = __ldg(pb + (size_t)64  * HWb);
        float b2 = __ldg(pb + (size_t)128 * HWb);
        float b3 = __ldg(pb + (size_t)192 * HWb);

        acc0 += a0 * wa;  acc1 += a1 * wa;
        acc2 += a2 * wa;  acc3 += a3 * wa;
        acc0 += b0 * wb;  acc1 += b1 * wb;
        acc2 += b2 * wb;  acc3 += b3 * wb;
    }
    if (k < ne) {
        const int ea = s_list[k];
        const int HWa = s_HW[ea];
        const float wa = s_w[ea][corner];
        const float* pa = s_ptr[ea][corner] + (size_t)chsub * HWa;
        acc0 += __ldg(pa)                     * wa;
        acc1 += __ldg(pa + (size_t)64  * HWa) * wa;
        acc2 += __ldg(pa + (size_t)128 * HWa) * wa;
        acc3 += __ldg(pa + (size_t)192 * HWa) * wa;
    }

    // single quad butterfly at the end (sum 4 corners)
    acc0 += __shfl_xor_sync(0xFFFFFFFFu, acc0, 1);
    acc1 += __shfl_xor_sync(0xFFFFFFFFu, acc1, 1);
    acc2 += __shfl_xor_sync(0xFFFFFFFFu, acc2, 1);
    acc3 += __shfl_xor_sync(0xFFFFFFFFu, acc3, 1);
    acc0 += __shfl_xor_sync(0xFFFFFFFFu, acc0, 2);
    acc1 += __shfl_xor_sync(0xFFFFFFFFu, acc1, 2);
    acc2 += __shfl_xor_sync(0xFFFFFFFFu, acc2, 2);
    acc3 += __shfl_xor_sync(0xFFFFFFFFu, acc3, 2);

    if (corner == 0) {
        const float s = 0.25f / (cnt + EPSV);
        float* o = out + (size_t)bm * CCH + chsub;
        o[0]   = acc0 * s;
        o[64]  = acc1 * s;
        o[128] = acc2 * s;
        o[192] = acc3 * s;
    }
}

extern "C" void kernel_launch(void* const* d_in, const int* in_sizes, int n_in,
                              void* d_out, int out_size)
{
    const float* f0  = (const float*)d_in[0];
    const float* f1  = (const float*)d_in[1];
    const float* f2  = (const float*)d_in[2];
    const float* f3  = (const float*)d_in[3];
    const float* rp  = (const float*)d_in[4];
    const float* l2i = (const float*)d_in[5];
    float* out = (float*)d_out;

    dim3 grid(BQ * MQ);
    dim3 block(CCH);
    FeatureSampler_kernel<<<grid, block>>>(f0, f1, f2, f3, rp, l2i, out);
}